// round 5
// baseline (speedup 1.0000x reference)
#include <cuda_runtime.h>
#include <cuda_fp16.h>
#include <math.h>
#include <stdint.h>

#define N_BATCH 4
#define C_DIM   256
#define P_DIM   4096
#define HB      0.5f
#define EPS     1e-5f
#define LOG2E   1.4426950408889634f

// ---------------- scratch ----------------------------------------------------
__device__ float  g_mu[C_DIM];
__device__ __half g_xh[(size_t)N_BATCH * C_DIM * P_DIM];   // centered (then scaled in place)
__device__ __half g_yh[(size_t)N_BATCH * C_DIM * P_DIM];
__device__ float  g_rx[N_BATCH * P_DIM];
__device__ float  g_ry[N_BATCH * P_DIM];
__device__ __half g_cosh[(size_t)N_BATCH * P_DIM * P_DIM]; // 128 MB
__device__ float  g_b2[N_BATCH * P_DIM];
__device__ float  g_bias[N_BATCH * P_DIM];
#define P_CHUNKS 8
__device__ float  g_colM[N_BATCH * P_CHUNKS * P_DIM];
__device__ float  g_cxpart[N_BATCH * 16];

__device__ __forceinline__ uint32_t smem_u32(const void* p) {
    uint32_t a;
    asm("{ .reg .u64 t; cvta.to.shared.u64 t, %1; cvt.u32.u64 %0, t; }" : "=r"(a) : "l"(p));
    return a;
}
__device__ __forceinline__ void h8_to_f(uint4 u, float* f) {
    __half2* h = (__half2*)&u;
    #pragma unroll
    for (int j = 0; j < 4; j++) {
        float2 p = __half22float2(h[j]);
        f[2 * j] = p.x; f[2 * j + 1] = p.y;
    }
}

// ---------------- K1: per-channel mean of y ----------------------------------
__global__ void k_mean(const float* __restrict__ y) {
    int c = blockIdx.x;
    int tid = threadIdx.x;
    float s = 0.f;
    for (int n = 0; n < N_BATCH; n++) {
        const float* base = y + ((size_t)n * C_DIM + c) * P_DIM;
        for (int p = tid; p < P_DIM; p += 256) s += base[p];
    }
    __shared__ float sm[256];
    sm[tid] = s; __syncthreads();
    for (int o = 128; o > 0; o >>= 1) {
        if (tid < o) sm[tid] += sm[tid + o];
        __syncthreads();
    }
    if (tid == 0) g_mu[c] = sm[0] * (1.f / (float)(N_BATCH * P_DIM));
}

// ---------------- K2a: center, write unscaled fp16, record rsqrt(sumsq) -----
__global__ __launch_bounds__(256) void k_norm1(const float* __restrict__ x,
                                               const float* __restrict__ y) {
    __shared__ float mu[C_DIM];
    int tid = threadIdx.x;
    if (tid < C_DIM) mu[tid] = g_mu[tid];
    __syncthreads();

    int idx = blockIdx.x * 256 + tid;
    int n = idx / P_DIM, p = idx % P_DIM;
    const float* xb = x + (size_t)n * C_DIM * P_DIM + p;
    const float* yb = y + (size_t)n * C_DIM * P_DIM + p;
    __half* xo = g_xh + (size_t)n * C_DIM * P_DIM + p;
    __half* yo = g_yh + (size_t)n * C_DIM * P_DIM + p;

    float sx = 0.f, sy = 0.f;
    #pragma unroll 8
    for (int c = 0; c < C_DIM; c++) {
        float m  = mu[c];
        float xv = xb[(size_t)c * P_DIM] - m;
        float yv = yb[(size_t)c * P_DIM] - m;
        sx += xv * xv;
        sy += yv * yv;
        xo[(size_t)c * P_DIM] = __float2half_rn(xv);
        yo[(size_t)c * P_DIM] = __float2half_rn(yv);
    }
    g_rx[idx] = rsqrtf(sx);
    g_ry[idx] = rsqrtf(sy);
}

// ---------------- K2b: scale in place ----------------------------------------
__global__ __launch_bounds__(256) void k_norm2() {
    int idx = blockIdx.x * 256 + threadIdx.x;
    int n = idx / P_DIM, p = idx % P_DIM;
    float rx = g_rx[idx], ry = g_ry[idx];
    __half* xo = g_xh + (size_t)n * C_DIM * P_DIM + p;
    __half* yo = g_yh + (size_t)n * C_DIM * P_DIM + p;
    #pragma unroll 8
    for (int c = 0; c < C_DIM; c++) {
        xo[(size_t)c * P_DIM] = __float2half_rn(__half2float(xo[(size_t)c * P_DIM]) * rx);
        yo[(size_t)c * P_DIM] = __float2half_rn(__half2float(yo[(size_t)c * P_DIM]) * ry);
    }
}

// ---------------- K3: fp16 mma GEMM  cos = A^T B  (block 256x128, warp 64x64)
#define BM 256
#define BN 128
#define BK 32
#define ASTAGE 16384    // 32 k * 256 m * 2B
#define BSTAGE 8192     // 32 k * 128 n * 2B

__device__ __forceinline__ void mma_f16(float* c, const uint32_t* a, const uint32_t* b) {
    asm volatile(
        "mma.sync.aligned.m16n8k16.row.col.f32.f16.f16.f32 "
        "{%0,%1,%2,%3},{%4,%5,%6,%7},{%8,%9},{%0,%1,%2,%3};\n"
        : "+f"(c[0]), "+f"(c[1]), "+f"(c[2]), "+f"(c[3])
        : "r"(a[0]), "r"(a[1]), "r"(a[2]), "r"(a[3]), "r"(b[0]), "r"(b[1]));
}
__device__ __forceinline__ void ldsm4t(uint32_t* r, uint32_t addr) {
    asm volatile("ldmatrix.sync.aligned.m8n8.x4.trans.shared.b16 {%0,%1,%2,%3},[%4];"
                 : "=r"(r[0]), "=r"(r[1]), "=r"(r[2]), "=r"(r[3]) : "r"(addr));
}

__global__ __launch_bounds__(256, 1) void k_gemm_h() {
    __shared__ char sm[2 * ASTAGE + 2 * BSTAGE];   // 48 KB: A0 A1 B0 B1

    int nb = blockIdx.z;
    const __half* A = g_xh + (size_t)nb * C_DIM * P_DIM;
    const __half* B = g_yh + (size_t)nb * C_DIM * P_DIM;
    __half* Cm      = g_cosh + (size_t)nb * P_DIM * P_DIM;

    int tid = threadIdx.x;
    int m0 = blockIdx.x * BM, n0 = blockIdx.y * BN;
    int warp = tid >> 5, lane = tid & 31;
    int wm = warp & 3, wn = warp >> 2;
    int g = lane >> 2, t = lane & 3;
    int lg = lane >> 3, lr = lane & 7;

    uint32_t smbase = smem_u32(sm);
    uint32_t smA[2] = { smbase, smbase + ASTAGE };
    uint32_t smB[2] = { smbase + 2 * ASTAGE, smbase + 2 * ASTAGE + BSTAGE };

    // load maps: A 4 vecs (16B) per thread per stage; B 2 vecs
    int akr[4], au[4], bkr[2], bu[2];
    #pragma unroll
    for (int v = 0; v < 4; v++) { int i = v * 256 + tid; akr[v] = i >> 5; au[v] = i & 31; }
    #pragma unroll
    for (int v = 0; v < 2; v++) { int i = v * 256 + tid; bkr[v] = i >> 4; bu[v] = i & 15; }

    uint4 ra[4], rb[2];
    float acc[4][8][4] = {};

    // prefetch stage 0
    #pragma unroll
    for (int v = 0; v < 4; v++)
        ra[v] = *(const uint4*)(A + (size_t)akr[v] * P_DIM + m0 + au[v] * 8);
    #pragma unroll
    for (int v = 0; v < 2; v++)
        rb[v] = *(const uint4*)(B + (size_t)bkr[v] * P_DIM + n0 + bu[v] * 8);
    #pragma unroll
    for (int v = 0; v < 4; v++)
        *(uint4*)(sm + (smA[0] - smbase) + akr[v] * 512 + ((au[v] ^ (akr[v] & 7)) << 4)) = ra[v];
    #pragma unroll
    for (int v = 0; v < 2; v++)
        *(uint4*)(sm + (smB[0] - smbase) + bkr[v] * 256 + ((bu[v] ^ (bkr[v] & 7)) << 4)) = rb[v];
    __syncthreads();

    int buf = 0;
    const int NST = C_DIM / BK;    // 8
    #pragma unroll 1
    for (int st = 0; st < NST; st++) {
        if (st + 1 < NST) {
            size_t koff = (size_t)(st + 1) * BK * P_DIM;
            #pragma unroll
            for (int v = 0; v < 4; v++)
                ra[v] = *(const uint4*)(A + koff + (size_t)akr[v] * P_DIM + m0 + au[v] * 8);
            #pragma unroll
            for (int v = 0; v < 2; v++)
                rb[v] = *(const uint4*)(B + koff + (size_t)bkr[v] * P_DIM + n0 + bu[v] * 8);
        }
        #pragma unroll
        for (int ks = 0; ks < BK; ks += 16) {
            uint32_t af[4][4], bf[8][2];
            int ak = ks + lr + ((lg >> 1) << 3);
            #pragma unroll
            for (int im = 0; im < 4; im++) {
                int mj = wm * 8 + im * 2 + (lg & 1);
                ldsm4t(af[im], smA[buf] + ak * 512 + ((mj ^ (ak & 7)) << 4));
            }
            int bk = ks + lr + ((lg & 1) << 3);
            #pragma unroll
            for (int jp = 0; jp < 4; jp++) {
                int njc = wn * 8 + jp * 2 + (lg >> 1);
                uint32_t r[4];
                ldsm4t(r, smB[buf] + bk * 256 + ((njc ^ (bk & 7)) << 4));
                bf[jp * 2][0] = r[0]; bf[jp * 2][1] = r[1];
                bf[jp * 2 + 1][0] = r[2]; bf[jp * 2 + 1][1] = r[3];
            }
            #pragma unroll
            for (int im = 0; im < 4; im++)
                #pragma unroll
                for (int jn = 0; jn < 8; jn++)
                    mma_f16(acc[im][jn], af[im], bf[jn]);
        }
        if (st + 1 < NST) {
            __syncthreads();
            int nb2 = buf ^ 1;
            #pragma unroll
            for (int v = 0; v < 4; v++)
                *(uint4*)(sm + (smA[nb2] - smbase) + akr[v] * 512 + ((au[v] ^ (akr[v] & 7)) << 4)) = ra[v];
            #pragma unroll
            for (int v = 0; v < 2; v++)
                *(uint4*)(sm + (smB[nb2] - smbase) + bkr[v] * 256 + ((bu[v] ^ (bkr[v] & 7)) << 4)) = rb[v];
            __syncthreads();
            buf = nb2;
        }
    }

    // fp16 epilogue
    #pragma unroll
    for (int im = 0; im < 4; im++) {
        #pragma unroll
        for (int jn = 0; jn < 8; jn++) {
            int m = m0 + wm * 64 + im * 16 + g;
            int n = n0 + wn * 64 + jn * 8 + t * 2;
            *(__half2*)&Cm[(size_t)m * P_DIM + n] =
                __floats2half2_rn(acc[im][jn][0], acc[im][jn][1]);
            *(__half2*)&Cm[(size_t)(m + 8) * P_DIM + n] =
                __floats2half2_rn(acc[im][jn][2], acc[im][jn][3]);
        }
    }
}

// ---------------- K4: per-row max -> b2, bias (fp16 row in registers) --------
__global__ __launch_bounds__(256) void k_row() {
    int row = blockIdx.x;                       // 0 .. N*P-1
    int tid = threadIdx.x;
    const uint4* r4 = (const uint4*)(g_cosh + (size_t)row * P_DIM);  // 512 uint4/row

    float v[16];
    uint4 u0 = r4[tid], u1 = r4[tid + 256];
    h8_to_f(u0, v);
    h8_to_f(u1, v + 8);

    float m = -1e30f;
    #pragma unroll
    for (int i = 0; i < 16; i++) m = fmaxf(m, v[i]);

    __shared__ float red[256];
    red[tid] = m; __syncthreads();
    for (int o = 128; o > 0; o >>= 1) {
        if (tid < o) red[tid] = fmaxf(red[tid], red[tid + o]);
        __syncthreads();
    }
    m = red[0];
    __syncthreads();

    float beta = 1.f / (HB * ((1.f - m) + EPS));
    float b2 = beta * LOG2E;

    float s = 0.f;
    #pragma unroll
    for (int i = 0; i < 16; i++) s += exp2f(b2 * (v[i] - m));

    red[tid] = s; __syncthreads();
    for (int o = 128; o > 0; o >>= 1) {
        if (tid < o) red[tid] += red[tid + o];
        __syncthreads();
    }
    if (tid == 0) {
        g_b2[row]   = b2;
        g_bias[row] = -b2 * m - log2f(red[0]);
    }
}

// ---------------- K5a: partial column max ------------------------------------
__global__ __launch_bounds__(256) void k_colA() {
    int n  = blockIdx.z;
    int pc = blockIdx.y;
    int q  = blockIdx.x * 256 + threadIdx.x;
    const int PC = P_DIM / P_CHUNKS;
    int p0 = pc * PC;

    const __half* cm = g_cosh + (size_t)n * P_DIM * P_DIM + q;
    const float* b2 = g_b2   + n * P_DIM;
    const float* bi = g_bias + n * P_DIM;

    float M = 0.f;
    #pragma unroll 8
    for (int p = p0; p < p0 + PC; p++) {
        float c = __half2float(cm[(size_t)p * P_DIM]);
        M = fmaxf(M, exp2f(fmaf(b2[p], c, bi[p])));
    }
    g_colM[(n * P_CHUNKS + pc) * P_DIM + q] = M;
}

// ---------------- K5b: finish column max, sum over q -------------------------
__global__ __launch_bounds__(256) void k_colB() {
    int n = blockIdx.y;
    int q = blockIdx.x * 256 + threadIdx.x;
    float M = 0.f;
    #pragma unroll
    for (int pc = 0; pc < P_CHUNKS; pc++)
        M = fmaxf(M, g_colM[(n * P_CHUNKS + pc) * P_DIM + q]);

    __shared__ float red[256];
    red[threadIdx.x] = M; __syncthreads();
    for (int o = 128; o > 0; o >>= 1) {
        if (threadIdx.x < o) red[threadIdx.x] += red[threadIdx.x + o];
        __syncthreads();
    }
    if (threadIdx.x == 0)
        g_cxpart[n * 16 + blockIdx.x] = red[0];
}

// ---------------- K6: final scalar loss --------------------------------------
__global__ void k_final(float* __restrict__ out) {
    if (threadIdx.x == 0) {
        float loss = 0.f;
        for (int n = 0; n < N_BATCH; n++) {
            float s = 0.f;
            for (int b = 0; b < 16; b++) s += g_cxpart[n * 16 + b];
            float cx = s * (1.f / (float)P_DIM);
            loss += -logf(cx + EPS);
        }
        out[0] = loss * (1.f / (float)N_BATCH);
    }
}

// ---------------- launch ------------------------------------------------------
extern "C" void kernel_launch(void* const* d_in, const int* in_sizes, int n_in,
                              void* d_out, int out_size) {
    const float* x = (const float*)d_in[0];
    const float* y = (const float*)d_in[1];
    float* out = (float*)d_out;

    k_mean<<<C_DIM, 256>>>(y);
    k_norm1<<<(N_BATCH * P_DIM) / 256, 256>>>(x, y);
    k_norm2<<<(N_BATCH * P_DIM) / 256, 256>>>();

    dim3 gg(P_DIM / BM, P_DIM / BN, N_BATCH);
    k_gemm_h<<<gg, 256>>>();

    k_row<<<N_BATCH * P_DIM, 256>>>();

    dim3 gca(P_DIM / 256, P_CHUNKS, N_BATCH);
    k_colA<<<gca, 256>>>();

    dim3 gcb(P_DIM / 256, N_BATCH);
    k_colB<<<gcb, 256>>>();

    k_final<<<1, 32>>>(out);
}

// round 6
// speedup vs baseline: 1.2570x; 1.2570x over previous
#include <cuda_runtime.h>
#include <cuda_fp16.h>
#include <math.h>
#include <stdint.h>

#define N_BATCH 4
#define C_DIM   256
#define P_DIM   4096
#define HB      0.5f
#define EPS     1e-5f
#define LOG2E   1.4426950408889634f

// ---------------- scratch ----------------------------------------------------
__device__ float  g_mu[C_DIM];
__device__ __half g_xh[(size_t)N_BATCH * C_DIM * P_DIM];   // [n][c][p] fp16 normalized
__device__ __half g_yh[(size_t)N_BATCH * C_DIM * P_DIM];
__device__ __half g_cosh[(size_t)N_BATCH * P_DIM * P_DIM]; // 128 MB
__device__ float  g_b2[N_BATCH * P_DIM];
__device__ float  g_bias[N_BATCH * P_DIM];
#define P_CHUNKS 8
__device__ float  g_colM[N_BATCH * P_CHUNKS * P_DIM];
__device__ float  g_cxpart[N_BATCH * 16];

__device__ __forceinline__ uint32_t smem_u32(const void* p) {
    uint32_t a;
    asm("{ .reg .u64 t; cvta.to.shared.u64 t, %1; cvt.u32.u64 %0, t; }" : "=r"(a) : "l"(p));
    return a;
}
__device__ __forceinline__ void h8_to_f(uint4 u, float* f) {
    __half2* h = (__half2*)&u;
    #pragma unroll
    for (int j = 0; j < 4; j++) {
        float2 p = __half22float2(h[j]);
        f[2 * j] = p.x; f[2 * j + 1] = p.y;
    }
}

// ---------------- K1: per-channel mean of y ----------------------------------
__global__ void k_mean(const float* __restrict__ y) {
    int c = blockIdx.x;
    int tid = threadIdx.x;
    float s = 0.f;
    for (int n = 0; n < N_BATCH; n++) {
        const float* base = y + ((size_t)n * C_DIM + c) * P_DIM;
        for (int p = tid; p < P_DIM; p += 256) s += base[p];
    }
    __shared__ float sm[256];
    sm[tid] = s; __syncthreads();
    for (int o = 128; o > 0; o >>= 1) {
        if (tid < o) sm[tid] += sm[tid + o];
        __syncthreads();
    }
    if (tid == 0) g_mu[c] = sm[0] * (1.f / (float)(N_BATCH * P_DIM));
}

// ---------------- K2: center + normalize -> fp16 (single pass, reads x,y 2x) -
__global__ __launch_bounds__(256) void k_norm(const float* __restrict__ x,
                                              const float* __restrict__ y) {
    __shared__ float mu[C_DIM];
    int tid = threadIdx.x;
    if (tid < C_DIM) mu[tid] = g_mu[tid];
    __syncthreads();

    int idx = blockIdx.x * 256 + tid;
    int n = idx / P_DIM, p = idx % P_DIM;
    const float* xb = x + (size_t)n * C_DIM * P_DIM + p;
    const float* yb = y + (size_t)n * C_DIM * P_DIM + p;

    float sx = 0.f, sy = 0.f;
    #pragma unroll 8
    for (int c = 0; c < C_DIM; c++) {
        float m  = mu[c];
        float xv = xb[(size_t)c * P_DIM] - m;
        float yv = yb[(size_t)c * P_DIM] - m;
        sx += xv * xv;
        sy += yv * yv;
    }
    float rx = rsqrtf(sx), ry = rsqrtf(sy);

    __half* xo = g_xh + (size_t)n * C_DIM * P_DIM + p;
    __half* yo = g_yh + (size_t)n * C_DIM * P_DIM + p;
    #pragma unroll 8
    for (int c = 0; c < C_DIM; c++) {
        float m = mu[c];
        xo[(size_t)c * P_DIM] = __float2half_rn((xb[(size_t)c * P_DIM] - m) * rx);
        yo[(size_t)c * P_DIM] = __float2half_rn((yb[(size_t)c * P_DIM] - m) * ry);
    }
}

// ---------------- K3: fp16 mma.sync GEMM  cos = A^T B (128x128, occ 2) -------
#define BM 128
#define BN 128
#define BK 32
#define STAGE_BYTES 8192      // 32 * 128 * 2

__device__ __forceinline__ void mma_f16(float* c, const uint32_t* a, const uint32_t* b) {
    asm volatile(
        "mma.sync.aligned.m16n8k16.row.col.f32.f16.f16.f32 "
        "{%0,%1,%2,%3},{%4,%5,%6,%7},{%8,%9},{%0,%1,%2,%3};\n"
        : "+f"(c[0]), "+f"(c[1]), "+f"(c[2]), "+f"(c[3])
        : "r"(a[0]), "r"(a[1]), "r"(a[2]), "r"(a[3]), "r"(b[0]), "r"(b[1]));
}
__device__ __forceinline__ void ldsm4t(uint32_t* r, uint32_t addr) {
    asm volatile("ldmatrix.sync.aligned.m8n8.x4.trans.shared.b16 {%0,%1,%2,%3},[%4];"
                 : "=r"(r[0]), "=r"(r[1]), "=r"(r[2]), "=r"(r[3]) : "r"(addr));
}

__global__ __launch_bounds__(256, 2) void k_gemm_h() {
    __shared__ char sm[4 * STAGE_BYTES];    // A0 A1 B0 B1

    int nb = blockIdx.z;
    const __half* A = g_xh + (size_t)nb * C_DIM * P_DIM;
    const __half* B = g_yh + (size_t)nb * C_DIM * P_DIM;
    __half* Cm      = g_cosh + (size_t)nb * P_DIM * P_DIM;

    int tid = threadIdx.x;
    int m0 = blockIdx.x * BM, n0 = blockIdx.y * BN;
    int warp = tid >> 5, lane = tid & 31;
    int wm = warp & 3, wn = warp >> 2;
    int g = lane >> 2, t = lane & 3;
    int lg = lane >> 3, lr = lane & 7;

    uint32_t smA[2] = { smem_u32(sm),                 smem_u32(sm) + STAGE_BYTES };
    uint32_t smB[2] = { smem_u32(sm) + 2*STAGE_BYTES, smem_u32(sm) + 3*STAGE_BYTES };

    int lk[2], lj[2];
    #pragma unroll
    for (int v = 0; v < 2; v++) {
        int idx = v * 256 + tid;
        lk[v] = idx >> 4;
        lj[v] = idx & 15;
    }

    uint4 ra[2], rb[2];
    float acc[2][8][4] = {};

    #pragma unroll
    for (int v = 0; v < 2; v++) {
        ra[v] = *(const uint4*)(A + (size_t)lk[v] * P_DIM + m0 + lj[v] * 8);
        rb[v] = *(const uint4*)(B + (size_t)lk[v] * P_DIM + n0 + lj[v] * 8);
    }
    #pragma unroll
    for (int v = 0; v < 2; v++) {
        uint32_t off = lk[v] * 256 + ((lj[v] ^ (lk[v] & 7)) << 4);
        *(uint4*)(sm + (smA[0] - smem_u32(sm)) + off) = ra[v];
        *(uint4*)(sm + (smB[0] - smem_u32(sm)) + off) = rb[v];
    }
    __syncthreads();

    int buf = 0;
    const int NST = C_DIM / BK;    // 8
    #pragma unroll 1
    for (int st = 0; st < NST; st++) {
        if (st + 1 < NST) {
            size_t koff = (size_t)(st + 1) * BK * P_DIM;
            #pragma unroll
            for (int v = 0; v < 2; v++) {
                ra[v] = *(const uint4*)(A + koff + (size_t)lk[v] * P_DIM + m0 + lj[v] * 8);
                rb[v] = *(const uint4*)(B + koff + (size_t)lk[v] * P_DIM + n0 + lj[v] * 8);
            }
        }
        #pragma unroll
        for (int ks = 0; ks < BK; ks += 16) {
            uint32_t af[2][4], bf[8][2];
            int ak = ks + lr + ((lg >> 1) << 3);
            #pragma unroll
            for (int im = 0; im < 2; im++) {
                int mj = ((wm * 32 + im * 16) >> 3) + (lg & 1);
                ldsm4t(af[im], smA[buf] + ak * 256 + ((mj ^ (ak & 7)) << 4));
            }
            int bk = ks + lr + ((lg & 1) << 3);
            #pragma unroll
            for (int jp = 0; jp < 4; jp++) {
                int njc = ((wn * 64 + jp * 16) >> 3) + (lg >> 1);
                uint32_t r[4];
                ldsm4t(r, smB[buf] + bk * 256 + ((njc ^ (bk & 7)) << 4));
                bf[jp * 2][0] = r[0]; bf[jp * 2][1] = r[1];
                bf[jp * 2 + 1][0] = r[2]; bf[jp * 2 + 1][1] = r[3];
            }
            #pragma unroll
            for (int im = 0; im < 2; im++)
                #pragma unroll
                for (int jn = 0; jn < 8; jn++)
                    mma_f16(acc[im][jn], af[im], bf[jn]);
        }
        if (st + 1 < NST) {
            __syncthreads();
            int nbuf = buf ^ 1;
            #pragma unroll
            for (int v = 0; v < 2; v++) {
                uint32_t off = lk[v] * 256 + ((lj[v] ^ (lk[v] & 7)) << 4);
                *(uint4*)(sm + (smA[nbuf] - smem_u32(sm)) + off) = ra[v];
                *(uint4*)(sm + (smB[nbuf] - smem_u32(sm)) + off) = rb[v];
            }
            __syncthreads();
            buf = nbuf;
        }
    }

    // fp16 epilogue
    #pragma unroll
    for (int im = 0; im < 2; im++) {
        #pragma unroll
        for (int jn = 0; jn < 8; jn++) {
            int m = m0 + wm * 32 + im * 16 + g;
            int n = n0 + wn * 64 + jn * 8 + t * 2;
            *(__half2*)&Cm[(size_t)m * P_DIM + n] =
                __floats2half2_rn(acc[im][jn][0], acc[im][jn][1]);
            *(__half2*)&Cm[(size_t)(m + 8) * P_DIM + n] =
                __floats2half2_rn(acc[im][jn][2], acc[im][jn][3]);
        }
    }
}

// ---------------- K4: per-row max -> b2, bias (fp16 row in registers) --------
__global__ __launch_bounds__(256) void k_row() {
    int row = blockIdx.x;                       // 0 .. N*P-1
    int tid = threadIdx.x;
    const uint4* r4 = (const uint4*)(g_cosh + (size_t)row * P_DIM);  // 512 uint4/row

    float v[16];
    uint4 u0 = r4[tid], u1 = r4[tid + 256];
    h8_to_f(u0, v);
    h8_to_f(u1, v + 8);

    float m = -1e30f;
    #pragma unroll
    for (int i = 0; i < 16; i++) m = fmaxf(m, v[i]);

    __shared__ float red[256];
    red[tid] = m; __syncthreads();
    for (int o = 128; o > 0; o >>= 1) {
        if (tid < o) red[tid] = fmaxf(red[tid], red[tid + o]);
        __syncthreads();
    }
    m = red[0];
    __syncthreads();

    float beta = 1.f / (HB * ((1.f - m) + EPS));
    float b2 = beta * LOG2E;

    float s = 0.f;
    #pragma unroll
    for (int i = 0; i < 16; i++) s += exp2f(b2 * (v[i] - m));

    red[tid] = s; __syncthreads();
    for (int o = 128; o > 0; o >>= 1) {
        if (tid < o) red[tid] += red[tid + o];
        __syncthreads();
    }
    if (tid == 0) {
        g_b2[row]   = b2;
        g_bias[row] = -b2 * m - log2f(red[0]);
    }
}

// ---------------- K5a: partial column max ------------------------------------
__global__ __launch_bounds__(256) void k_colA() {
    int n  = blockIdx.z;
    int pc = blockIdx.y;
    int q  = blockIdx.x * 256 + threadIdx.x;
    const int PC = P_DIM / P_CHUNKS;
    int p0 = pc * PC;

    const __half* cm = g_cosh + (size_t)n * P_DIM * P_DIM + q;
    const float* b2 = g_b2   + n * P_DIM;
    const float* bi = g_bias + n * P_DIM;

    float M = 0.f;
    #pragma unroll 8
    for (int p = p0; p < p0 + PC; p++) {
        float c = __half2float(cm[(size_t)p * P_DIM]);
        M = fmaxf(M, exp2f(fmaf(b2[p], c, bi[p])));
    }
    g_colM[(n * P_CHUNKS + pc) * P_DIM + q] = M;
}

// ---------------- K5b: finish column max, sum over q -------------------------
__global__ __launch_bounds__(256) void k_colB() {
    int n = blockIdx.y;
    int q = blockIdx.x * 256 + threadIdx.x;
    float M = 0.f;
    #pragma unroll
    for (int pc = 0; pc < P_CHUNKS; pc++)
        M = fmaxf(M, g_colM[(n * P_CHUNKS + pc) * P_DIM + q]);

    __shared__ float red[256];
    red[threadIdx.x] = M; __syncthreads();
    for (int o = 128; o > 0; o >>= 1) {
        if (threadIdx.x < o) red[threadIdx.x] += red[threadIdx.x + o];
        __syncthreads();
    }
    if (threadIdx.x == 0)
        g_cxpart[n * 16 + blockIdx.x] = red[0];
}

// ---------------- K6: final scalar loss --------------------------------------
__global__ void k_final(float* __restrict__ out) {
    if (threadIdx.x == 0) {
        float loss = 0.f;
        for (int n = 0; n < N_BATCH; n++) {
            float s = 0.f;
            for (int b = 0; b < 16; b++) s += g_cxpart[n * 16 + b];
            float cx = s * (1.f / (float)P_DIM);
            loss += -logf(cx + EPS);
        }
        out[0] = loss * (1.f / (float)N_BATCH);
    }
}

// ---------------- launch ------------------------------------------------------
extern "C" void kernel_launch(void* const* d_in, const int* in_sizes, int n_in,
                              void* d_out, int out_size) {
    const float* x = (const float*)d_in[0];
    const float* y = (const float*)d_in[1];
    float* out = (float*)d_out;

    k_mean<<<C_DIM, 256>>>(y);
    k_norm<<<(N_BATCH * P_DIM) / 256, 256>>>(x, y);

    dim3 gg(P_DIM / BM, P_DIM / BN, N_BATCH);
    k_gemm_h<<<gg, 256>>>();

    k_row<<<N_BATCH * P_DIM, 256>>>();

    dim3 gca(P_DIM / 256, P_CHUNKS, N_BATCH);
    k_colA<<<gca, 256>>>();

    dim3 gcb(P_DIM / 256, N_BATCH);
    k_colB<<<gcb, 256>>>();

    k_final<<<1, 32>>>(out);
}

// round 7
// speedup vs baseline: 1.2900x; 1.0263x over previous
#include <cuda_runtime.h>
#include <cuda_fp16.h>
#include <math.h>
#include <stdint.h>

#define N_BATCH 4
#define C_DIM   256
#define P_DIM   4096
#define HB      0.5f
#define EPS     1e-5f
#define LOG2E   1.4426950408889634f

// ---------------- scratch ----------------------------------------------------
__device__ float  g_mu[C_DIM];
__device__ __half g_xh[(size_t)N_BATCH * C_DIM * P_DIM];   // [n][c][p] fp16 normalized
__device__ __half g_yh[(size_t)N_BATCH * C_DIM * P_DIM];
__device__ __half g_cosh[(size_t)N_BATCH * P_DIM * P_DIM]; // 128 MB
__device__ float  g_b2[N_BATCH * P_DIM];
__device__ float  g_bias[N_BATCH * P_DIM];
#define P_CHUNKS 8
__device__ float  g_colM[N_BATCH * P_CHUNKS * P_DIM];      // partial col max of t (pre-exp)
__device__ float  g_cxpart[N_BATCH * 16];

__device__ __forceinline__ uint32_t smem_u32(const void* p) {
    uint32_t a;
    asm("{ .reg .u64 t; cvta.to.shared.u64 t, %1; cvt.u32.u64 %0, t; }" : "=r"(a) : "l"(p));
    return a;
}
__device__ __forceinline__ void h8_to_f(uint4 u, float* f) {
    __half2* h = (__half2*)&u;
    #pragma unroll
    for (int j = 0; j < 4; j++) {
        float2 p = __half22float2(h[j]);
        f[2 * j] = p.x; f[2 * j + 1] = p.y;
    }
}
__device__ __forceinline__ void cpasync16(uint32_t smaddr, const void* gptr) {
    asm volatile("cp.async.cg.shared.global [%0], [%1], 16;" :: "r"(smaddr), "l"(gptr));
}

// ---------------- K1: per-channel mean of y ----------------------------------
__global__ void k_mean(const float* __restrict__ y) {
    int c = blockIdx.x;
    int tid = threadIdx.x;
    float s = 0.f;
    for (int n = 0; n < N_BATCH; n++) {
        const float* base = y + ((size_t)n * C_DIM + c) * P_DIM;
        for (int p = tid; p < P_DIM; p += 256) s += base[p];
    }
    __shared__ float sm[256];
    sm[tid] = s; __syncthreads();
    for (int o = 128; o > 0; o >>= 1) {
        if (tid < o) sm[tid] += sm[tid + o];
        __syncthreads();
    }
    if (tid == 0) g_mu[c] = sm[0] * (1.f / (float)(N_BATCH * P_DIM));
}

// ---------------- K2: center + normalize -> fp16 -----------------------------
__global__ __launch_bounds__(256) void k_norm(const float* __restrict__ x,
                                              const float* __restrict__ y) {
    __shared__ float mu[C_DIM];
    int tid = threadIdx.x;
    if (tid < C_DIM) mu[tid] = g_mu[tid];
    __syncthreads();

    int idx = blockIdx.x * 256 + tid;
    int n = idx / P_DIM, p = idx % P_DIM;
    const float* xb = x + (size_t)n * C_DIM * P_DIM + p;
    const float* yb = y + (size_t)n * C_DIM * P_DIM + p;

    float sx = 0.f, sy = 0.f;
    #pragma unroll 8
    for (int c = 0; c < C_DIM; c++) {
        float m  = mu[c];
        float xv = xb[(size_t)c * P_DIM] - m;
        float yv = yb[(size_t)c * P_DIM] - m;
        sx += xv * xv;
        sy += yv * yv;
    }
    float rx = rsqrtf(sx), ry = rsqrtf(sy);

    __half* xo = g_xh + (size_t)n * C_DIM * P_DIM + p;
    __half* yo = g_yh + (size_t)n * C_DIM * P_DIM + p;
    #pragma unroll 8
    for (int c = 0; c < C_DIM; c++) {
        float m = mu[c];
        xo[(size_t)c * P_DIM] = __float2half_rn((xb[(size_t)c * P_DIM] - m) * rx);
        yo[(size_t)c * P_DIM] = __float2half_rn((yb[(size_t)c * P_DIM] - m) * ry);
    }
}

// ---------------- K3: fp16 mma GEMM, cp.async 3-stage ------------------------
#define BM 128
#define BN 128
#define BK 32
#define STG 8192      // bytes per A (or B) stage: 32 k * 128 * 2B

__device__ __forceinline__ void mma_f16(float* c, const uint32_t* a, const uint32_t* b) {
    asm volatile(
        "mma.sync.aligned.m16n8k16.row.col.f32.f16.f16.f32 "
        "{%0,%1,%2,%3},{%4,%5,%6,%7},{%8,%9},{%0,%1,%2,%3};\n"
        : "+f"(c[0]), "+f"(c[1]), "+f"(c[2]), "+f"(c[3])
        : "r"(a[0]), "r"(a[1]), "r"(a[2]), "r"(a[3]), "r"(b[0]), "r"(b[1]));
}
__device__ __forceinline__ void ldsm4t(uint32_t* r, uint32_t addr) {
    asm volatile("ldmatrix.sync.aligned.m8n8.x4.trans.shared.b16 {%0,%1,%2,%3},[%4];"
                 : "=r"(r[0]), "=r"(r[1]), "=r"(r[2]), "=r"(r[3]) : "r"(addr));
}

__global__ __launch_bounds__(256, 2) void k_gemm_h() {
    __shared__ char sm[6 * STG];    // A0 A1 A2 B0 B1 B2 = 48 KB

    int nb = blockIdx.z;
    const __half* A = g_xh + (size_t)nb * C_DIM * P_DIM;
    const __half* B = g_yh + (size_t)nb * C_DIM * P_DIM;
    __half* Cm      = g_cosh + (size_t)nb * P_DIM * P_DIM;

    int tid = threadIdx.x;
    int m0 = blockIdx.x * BM, n0 = blockIdx.y * BN;
    int warp = tid >> 5, lane = tid & 31;
    int wm = warp & 3, wn = warp >> 2;
    int g = lane >> 2, t = lane & 3;
    int lg = lane >> 3, lr = lane & 7;

    uint32_t smbase = smem_u32(sm);
    uint32_t smA[3] = { smbase, smbase + STG, smbase + 2 * STG };
    uint32_t smB[3] = { smbase + 3 * STG, smbase + 4 * STG, smbase + 5 * STG };

    // per-thread copy map: 2 x 16B for A, 2 x 16B for B per stage
    int lk[2], lj[2];
    uint32_t soff[2];
    #pragma unroll
    for (int v = 0; v < 2; v++) {
        int idx = v * 256 + tid;
        lk[v] = idx >> 4;
        lj[v] = idx & 15;
        soff[v] = lk[v] * 256 + ((lj[v] ^ (lk[v] & 7)) << 4);
    }

    const int NST = C_DIM / BK;    // 8

    // issue a stage's cp.asyncs + commit
    #define ISSUE(st, sb)                                                          \
    {                                                                              \
        size_t koff_ = (size_t)(st) * BK * P_DIM;                                  \
        _Pragma("unroll")                                                          \
        for (int v = 0; v < 2; v++) {                                              \
            cpasync16(smA[sb] + soff[v], A + koff_ + (size_t)lk[v] * P_DIM + m0 + lj[v] * 8); \
            cpasync16(smB[sb] + soff[v], B + koff_ + (size_t)lk[v] * P_DIM + n0 + lj[v] * 8); \
        }                                                                          \
        asm volatile("cp.async.commit_group;");                                    \
    }

    float acc[2][8][4] = {};

    ISSUE(0, 0);
    ISSUE(1, 1);

    #pragma unroll 1
    for (int st = 0; st < NST; st++) {
        asm volatile("cp.async.wait_group 1;" ::: "memory");
        __syncthreads();
        if (st + 2 < NST) ISSUE(st + 2, (st + 2) % 3);
        int buf = st % 3;

        #pragma unroll
        for (int ks = 0; ks < BK; ks += 16) {
            uint32_t af[2][4], bf[8][2];
            int ak = ks + lr + ((lg >> 1) << 3);
            #pragma unroll
            for (int im = 0; im < 2; im++) {
                int mj = ((wm * 32 + im * 16) >> 3) + (lg & 1);
                ldsm4t(af[im], smA[buf] + ak * 256 + ((mj ^ (ak & 7)) << 4));
            }
            int bk = ks + lr + ((lg & 1) << 3);
            #pragma unroll
            for (int jp = 0; jp < 4; jp++) {
                int njc = ((wn * 64 + jp * 16) >> 3) + (lg >> 1);
                uint32_t r[4];
                ldsm4t(r, smB[buf] + bk * 256 + ((njc ^ (bk & 7)) << 4));
                bf[jp * 2][0] = r[0]; bf[jp * 2][1] = r[1];
                bf[jp * 2 + 1][0] = r[2]; bf[jp * 2 + 1][1] = r[3];
            }
            #pragma unroll
            for (int im = 0; im < 2; im++)
                #pragma unroll
                for (int jn = 0; jn < 8; jn++)
                    mma_f16(acc[im][jn], af[im], bf[jn]);
        }
        __syncthreads();   // all warps done with buf st%3 before it is re-issued
    }

    // fp16 epilogue
    #pragma unroll
    for (int im = 0; im < 2; im++) {
        #pragma unroll
        for (int jn = 0; jn < 8; jn++) {
            int m = m0 + wm * 32 + im * 16 + g;
            int n = n0 + wn * 64 + jn * 8 + t * 2;
            *(__half2*)&Cm[(size_t)m * P_DIM + n] =
                __floats2half2_rn(acc[im][jn][0], acc[im][jn][1]);
            *(__half2*)&Cm[(size_t)(m + 8) * P_DIM + n] =
                __floats2half2_rn(acc[im][jn][2], acc[im][jn][3]);
        }
    }
}

// ---------------- K4: per-row max -> b2, bias --------------------------------
__global__ __launch_bounds__(256) void k_row() {
    int row = blockIdx.x;                       // 0 .. N*P-1
    int tid = threadIdx.x;
    const uint4* r4 = (const uint4*)(g_cosh + (size_t)row * P_DIM);

    float v[16];
    uint4 u0 = r4[tid], u1 = r4[tid + 256];
    h8_to_f(u0, v);
    h8_to_f(u1, v + 8);

    float m = -1e30f;
    #pragma unroll
    for (int i = 0; i < 16; i++) m = fmaxf(m, v[i]);

    __shared__ float red[256];
    red[tid] = m; __syncthreads();
    for (int o = 128; o > 0; o >>= 1) {
        if (tid < o) red[tid] = fmaxf(red[tid], red[tid + o]);
        __syncthreads();
    }
    m = red[0];
    __syncthreads();

    float beta = 1.f / (HB * ((1.f - m) + EPS));
    float b2 = beta * LOG2E;

    float s = 0.f;
    #pragma unroll
    for (int i = 0; i < 16; i++) s += exp2f(b2 * (v[i] - m));

    red[tid] = s; __syncthreads();
    for (int o = 128; o > 0; o >>= 1) {
        if (tid < o) red[tid] += red[tid + o];
        __syncthreads();
    }
    if (tid == 0) {
        g_b2[row]   = b2;
        g_bias[row] = -b2 * m - log2f(red[0]);
    }
}

// ---------------- K5a: partial column max of t = b2*c + bias (NO exp) --------
__global__ __launch_bounds__(256) void k_colA() {
    int n  = blockIdx.z;
    int pc = blockIdx.y;
    int q0 = (blockIdx.x * 256 + threadIdx.x) * 2;    // grid.x = P_DIM/512 = 8
    const int PC = P_DIM / P_CHUNKS;                  // 512
    int p0 = pc * PC;

    const __half2* cm = (const __half2*)(g_cosh + (size_t)n * P_DIM * P_DIM + q0);
    const float* b2 = g_b2   + n * P_DIM;
    const float* bi = g_bias + n * P_DIM;

    float M0 = -1e30f, M1 = -1e30f;
    #pragma unroll 8
    for (int p = p0; p < p0 + PC; p++) {
        float2 c = __half22float2(cm[(size_t)p * (P_DIM / 2)]);
        float bb = b2[p], bs = bi[p];
        M0 = fmaxf(M0, fmaf(bb, c.x, bs));
        M1 = fmaxf(M1, fmaf(bb, c.y, bs));
    }
    *(float2*)&g_colM[(n * P_CHUNKS + pc) * P_DIM + q0] = make_float2(M0, M1);
}

// ---------------- K5b: finish col max, one exp2 per q, sum -------------------
__global__ __launch_bounds__(256) void k_colB() {
    int n = blockIdx.y;
    int q0 = (blockIdx.x * 256 + threadIdx.x) * 2;    // grid.x = 8
    float M0 = -1e30f, M1 = -1e30f;
    #pragma unroll
    for (int pc = 0; pc < P_CHUNKS; pc++) {
        float2 v = *(const float2*)&g_colM[(n * P_CHUNKS + pc) * P_DIM + q0];
        M0 = fmaxf(M0, v.x);
        M1 = fmaxf(M1, v.y);
    }
    float s = exp2f(M0) + exp2f(M1);

    __shared__ float red[256];
    red[threadIdx.x] = s; __syncthreads();
    for (int o = 128; o > 0; o >>= 1) {
        if (threadIdx.x < o) red[threadIdx.x] += red[threadIdx.x + o];
        __syncthreads();
    }
    if (threadIdx.x == 0)
        g_cxpart[n * 8 + blockIdx.x] = red[0];
}

// ---------------- K6: final scalar loss --------------------------------------
__global__ void k_final(float* __restrict__ out) {
    if (threadIdx.x == 0) {
        float loss = 0.f;
        for (int n = 0; n < N_BATCH; n++) {
            float s = 0.f;
            for (int b = 0; b < 8; b++) s += g_cxpart[n * 8 + b];
            float cx = s * (1.f / (float)P_DIM);
            loss += -logf(cx + EPS);
        }
        out[0] = loss * (1.f / (float)N_BATCH);
    }
}

// ---------------- launch ------------------------------------------------------
extern "C" void kernel_launch(void* const* d_in, const int* in_sizes, int n_in,
                              void* d_out, int out_size) {
    const float* x = (const float*)d_in[0];
    const float* y = (const float*)d_in[1];
    float* out = (float*)d_out;

    k_mean<<<C_DIM, 256>>>(y);
    k_norm<<<(N_BATCH * P_DIM) / 256, 256>>>(x, y);

    dim3 gg(P_DIM / BM, P_DIM / BN, N_BATCH);
    k_gemm_h<<<gg, 256>>>();

    k_row<<<N_BATCH * P_DIM, 256>>>();

    dim3 gca(P_DIM / 512, P_CHUNKS, N_BATCH);
    k_colA<<<gca, 256>>>();

    dim3 gcb(P_DIM / 512, N_BATCH);
    k_colB<<<gcb, 256>>>();

    k_final<<<1, 32>>>(out);
}

// round 8
// speedup vs baseline: 1.5607x; 1.2099x over previous
#include <cuda_runtime.h>
#include <cuda_fp16.h>
#include <math.h>
#include <stdint.h>

#define N_BATCH 4
#define C_DIM   256
#define P_DIM   4096
#define HB      0.5f
#define EPS     1e-5f
#define LOG2E   1.4426950408889634f

// ---------------- scratch ----------------------------------------------------
__device__ float  g_mu[C_DIM];
__device__ __half g_xh[(size_t)N_BATCH * C_DIM * P_DIM];   // [n][c][p] fp16 normalized
__device__ __half g_yh[(size_t)N_BATCH * C_DIM * P_DIM];
__device__ __half g_cosh[(size_t)N_BATCH * P_DIM * P_DIM]; // 128 MB
#define R_CHUNK 32
#define N_RCH   (P_DIM / R_CHUNK)                          // 128 row-groups per batch
__device__ float  g_colM[(size_t)N_BATCH * N_RCH * P_DIM]; // 8 MB partial col maxes of t
__device__ float  g_cxpart[N_BATCH * 8];

__device__ __forceinline__ uint32_t smem_u32(const void* p) {
    uint32_t a;
    asm("{ .reg .u64 t; cvta.to.shared.u64 t, %1; cvt.u32.u64 %0, t; }" : "=r"(a) : "l"(p));
    return a;
}
__device__ __forceinline__ void h8_to_f(uint4 u, float* f) {
    __half2* h = (__half2*)&u;
    #pragma unroll
    for (int j = 0; j < 4; j++) {
        float2 p = __half22float2(h[j]);
        f[2 * j] = p.x; f[2 * j + 1] = p.y;
    }
}
__device__ __forceinline__ void cpasync16(uint32_t smaddr, const void* gptr) {
    asm volatile("cp.async.cg.shared.global [%0], [%1], 16;" :: "r"(smaddr), "l"(gptr));
}

// ---------------- K1: per-channel mean of y ----------------------------------
__global__ void k_mean(const float* __restrict__ y) {
    int c = blockIdx.x;
    int tid = threadIdx.x;
    float s = 0.f;
    for (int n = 0; n < N_BATCH; n++) {
        const float* base = y + ((size_t)n * C_DIM + c) * P_DIM;
        for (int p = tid; p < P_DIM; p += 256) s += base[p];
    }
    __shared__ float sm[256];
    sm[tid] = s; __syncthreads();
    for (int o = 128; o > 0; o >>= 1) {
        if (tid < o) sm[tid] += sm[tid + o];
        __syncthreads();
    }
    if (tid == 0) g_mu[c] = sm[0] * (1.f / (float)(N_BATCH * P_DIM));
}

// ---------------- K2: center + normalize -> fp16 -----------------------------
__global__ __launch_bounds__(256) void k_norm(const float* __restrict__ x,
                                              const float* __restrict__ y) {
    __shared__ float mu[C_DIM];
    int tid = threadIdx.x;
    if (tid < C_DIM) mu[tid] = g_mu[tid];
    __syncthreads();

    int idx = blockIdx.x * 256 + tid;
    int n = idx / P_DIM, p = idx % P_DIM;
    const float* xb = x + (size_t)n * C_DIM * P_DIM + p;
    const float* yb = y + (size_t)n * C_DIM * P_DIM + p;

    float sx = 0.f, sy = 0.f;
    #pragma unroll 8
    for (int c = 0; c < C_DIM; c++) {
        float m  = mu[c];
        float xv = xb[(size_t)c * P_DIM] - m;
        float yv = yb[(size_t)c * P_DIM] - m;
        sx += xv * xv;
        sy += yv * yv;
    }
    float rx = rsqrtf(sx), ry = rsqrtf(sy);

    __half* xo = g_xh + (size_t)n * C_DIM * P_DIM + p;
    __half* yo = g_yh + (size_t)n * C_DIM * P_DIM + p;
    #pragma unroll 8
    for (int c = 0; c < C_DIM; c++) {
        float m = mu[c];
        xo[(size_t)c * P_DIM] = __float2half_rn((xb[(size_t)c * P_DIM] - m) * rx);
        yo[(size_t)c * P_DIM] = __float2half_rn((yb[(size_t)c * P_DIM] - m) * ry);
    }
}

// ---------------- K3: fp16 mma GEMM, 4 warps x (64x64), cp.async 3-stage -----
#define BM 128
#define BN 128
#define BK 32
#define STG 8192      // bytes per A (or B) stage: 32 k * 128 * 2B

__device__ __forceinline__ void mma_f16(float* c, const uint32_t* a, const uint32_t* b) {
    asm volatile(
        "mma.sync.aligned.m16n8k16.row.col.f32.f16.f16.f32 "
        "{%0,%1,%2,%3},{%4,%5,%6,%7},{%8,%9},{%0,%1,%2,%3};\n"
        : "+f"(c[0]), "+f"(c[1]), "+f"(c[2]), "+f"(c[3])
        : "r"(a[0]), "r"(a[1]), "r"(a[2]), "r"(a[3]), "r"(b[0]), "r"(b[1]));
}
__device__ __forceinline__ void ldsm4t(uint32_t* r, uint32_t addr) {
    asm volatile("ldmatrix.sync.aligned.m8n8.x4.trans.shared.b16 {%0,%1,%2,%3},[%4];"
                 : "=r"(r[0]), "=r"(r[1]), "=r"(r[2]), "=r"(r[3]) : "r"(addr));
}

__global__ __launch_bounds__(128, 2) void k_gemm_h() {
    __shared__ char sm[6 * STG];    // A0 A1 A2 B0 B1 B2 = 48 KB

    int nb = blockIdx.z;
    const __half* A = g_xh + (size_t)nb * C_DIM * P_DIM;
    const __half* B = g_yh + (size_t)nb * C_DIM * P_DIM;
    __half* Cm      = g_cosh + (size_t)nb * P_DIM * P_DIM;

    int tid = threadIdx.x;
    int m0 = blockIdx.x * BM, n0 = blockIdx.y * BN;
    int warp = tid >> 5, lane = tid & 31;
    int wm = warp & 1, wn = warp >> 1;
    int g = lane >> 2, t = lane & 3;
    int lg = lane >> 3, lr = lane & 7;

    uint32_t smbase = smem_u32(sm);
    uint32_t smA[3] = { smbase, smbase + STG, smbase + 2 * STG };
    uint32_t smB[3] = { smbase + 3 * STG, smbase + 4 * STG, smbase + 5 * STG };

    // per-thread copy map: 4 x 16B for A, 4 x 16B for B per stage (128 threads)
    int lk[4], lj[4];
    uint32_t soff[4];
    #pragma unroll
    for (int v = 0; v < 4; v++) {
        int idx = v * 128 + tid;
        lk[v] = idx >> 4;
        lj[v] = idx & 15;
        soff[v] = lk[v] * 256 + ((lj[v] ^ (lk[v] & 7)) << 4);
    }

    const int NST = C_DIM / BK;    // 8

    #define ISSUE(st, sb)                                                          \
    {                                                                              \
        size_t koff_ = (size_t)(st) * BK * P_DIM;                                  \
        _Pragma("unroll")                                                          \
        for (int v = 0; v < 4; v++) {                                              \
            cpasync16(smA[sb] + soff[v], A + koff_ + (size_t)lk[v] * P_DIM + m0 + lj[v] * 8); \
            cpasync16(smB[sb] + soff[v], B + koff_ + (size_t)lk[v] * P_DIM + n0 + lj[v] * 8); \
        }                                                                          \
        asm volatile("cp.async.commit_group;");                                    \
    }

    float acc[4][8][4] = {};

    ISSUE(0, 0);
    ISSUE(1, 1);

    #pragma unroll 1
    for (int st = 0; st < NST; st++) {
        asm volatile("cp.async.wait_group 1;" ::: "memory");
        __syncthreads();
        if (st + 2 < NST) ISSUE(st + 2, (st + 2) % 3);
        int buf = st % 3;

        #pragma unroll
        for (int ks = 0; ks < BK; ks += 16) {
            uint32_t af[4][4], bf[8][2];
            int ak = ks + lr + ((lg >> 1) << 3);
            #pragma unroll
            for (int im = 0; im < 4; im++) {
                int mj = wm * 8 + im * 2 + (lg & 1);
                ldsm4t(af[im], smA[buf] + ak * 256 + ((mj ^ (ak & 7)) << 4));
            }
            int bk = ks + lr + ((lg & 1) << 3);
            #pragma unroll
            for (int jp = 0; jp < 4; jp++) {
                int njc = wn * 8 + jp * 2 + (lg >> 1);
                uint32_t r[4];
                ldsm4t(r, smB[buf] + bk * 256 + ((njc ^ (bk & 7)) << 4));
                bf[jp * 2][0] = r[0]; bf[jp * 2][1] = r[1];
                bf[jp * 2 + 1][0] = r[2]; bf[jp * 2 + 1][1] = r[3];
            }
            #pragma unroll
            for (int im = 0; im < 4; im++)
                #pragma unroll
                for (int jn = 0; jn < 8; jn++)
                    mma_f16(acc[im][jn], af[im], bf[jn]);
        }
        __syncthreads();
    }

    // fp16 epilogue
    #pragma unroll
    for (int im = 0; im < 4; im++) {
        #pragma unroll
        for (int jn = 0; jn < 8; jn++) {
            int m = m0 + wm * 64 + im * 16 + g;
            int n = n0 + wn * 64 + jn * 8 + t * 2;
            *(__half2*)&Cm[(size_t)m * P_DIM + n] =
                __floats2half2_rn(acc[im][jn][0], acc[im][jn][1]);
            *(__half2*)&Cm[(size_t)(m + 8) * P_DIM + n] =
                __floats2half2_rn(acc[im][jn][2], acc[im][jn][3]);
        }
    }
}

// ---------------- K4: fused row stats + column-max of t (single cos read) ----
// Block handles 32 rows. Per row: values in regs, block max -> beta/b2,
// sum exp2 -> bias; per-thread colmax of t accumulates in 16 registers.
__global__ __launch_bounds__(256) void k_rowcol() {
    int blk = blockIdx.x;              // 0 .. N*P/32-1
    int tid = threadIdx.x;
    int warp = tid >> 5, lane = tid & 31;
    int row0 = blk * R_CHUNK;

    __shared__ float red[2][16];       // [parity][0..7 max | 8..15 sum]

    float colmax[16];
    #pragma unroll
    for (int i = 0; i < 16; i++) colmax[i] = -1e30f;

    #pragma unroll 1
    for (int r = 0; r < R_CHUNK; r++) {
        int row = row0 + r;
        const uint4* r4 = (const uint4*)(g_cosh + (size_t)row * P_DIM);
        float v[16];
        uint4 u0 = r4[tid], u1 = r4[tid + 256];
        h8_to_f(u0, v);
        h8_to_f(u1, v + 8);

        float m = v[0];
        #pragma unroll
        for (int i = 1; i < 16; i++) m = fmaxf(m, v[i]);
        #pragma unroll
        for (int o = 16; o > 0; o >>= 1)
            m = fmaxf(m, __shfl_xor_sync(0xffffffffu, m, o));
        int par = r & 1;
        if (lane == 0) red[par][warp] = m;
        __syncthreads();
        m = red[par][0];
        #pragma unroll
        for (int w = 1; w < 8; w++) m = fmaxf(m, red[par][w]);

        float beta = 1.f / (HB * ((1.f - m) + EPS));
        float b2 = beta * LOG2E;

        float s = 0.f;
        #pragma unroll
        for (int i = 0; i < 16; i++) s += exp2f(b2 * (v[i] - m));
        #pragma unroll
        for (int o = 16; o > 0; o >>= 1)
            s += __shfl_xor_sync(0xffffffffu, s, o);
        if (lane == 0) red[par][8 + warp] = s;
        __syncthreads();
        s = red[par][8];
        #pragma unroll
        for (int w = 1; w < 8; w++) s += red[par][8 + w];

        float bias = -b2 * m - log2f(s);
        #pragma unroll
        for (int i = 0; i < 16; i++)
            colmax[i] = fmaxf(colmax[i], fmaf(b2, v[i], bias));
    }

    // write partials: thread owns q = tid*8..+7 and 2048 + tid*8..+7
    float* out = g_colM + (size_t)blk * P_DIM;
    *(float4*)&out[tid * 8]        = make_float4(colmax[0], colmax[1], colmax[2], colmax[3]);
    *(float4*)&out[tid * 8 + 4]    = make_float4(colmax[4], colmax[5], colmax[6], colmax[7]);
    *(float4*)&out[2048 + tid * 8]     = make_float4(colmax[8],  colmax[9],  colmax[10], colmax[11]);
    *(float4*)&out[2048 + tid * 8 + 4] = make_float4(colmax[12], colmax[13], colmax[14], colmax[15]);
}

// ---------------- K5: finish col max, one exp2 per q, sum --------------------
__global__ __launch_bounds__(256) void k_colB() {
    int n = blockIdx.y;
    int q0 = (blockIdx.x * 256 + threadIdx.x) * 2;    // grid.x = 8
    const float* cmn = g_colM + (size_t)n * N_RCH * P_DIM;
    float M0 = -1e30f, M1 = -1e30f;
    #pragma unroll 4
    for (int pc = 0; pc < N_RCH; pc++) {
        float2 v = *(const float2*)&cmn[(size_t)pc * P_DIM + q0];
        M0 = fmaxf(M0, v.x);
        M1 = fmaxf(M1, v.y);
    }
    float s = exp2f(M0) + exp2f(M1);

    __shared__ float red[256];
    red[threadIdx.x] = s; __syncthreads();
    for (int o = 128; o > 0; o >>= 1) {
        if (threadIdx.x < o) red[threadIdx.x] += red[threadIdx.x + o];
        __syncthreads();
    }
    if (threadIdx.x == 0)
        g_cxpart[n * 8 + blockIdx.x] = red[0];
}

// ---------------- K6: final scalar loss --------------------------------------
__global__ void k_final(float* __restrict__ out) {
    if (threadIdx.x == 0) {
        float loss = 0.f;
        for (int n = 0; n < N_BATCH; n++) {
            float s = 0.f;
            for (int b = 0; b < 8; b++) s += g_cxpart[n * 8 + b];
            float cx = s * (1.f / (float)P_DIM);
            loss += -logf(cx + EPS);
        }
        out[0] = loss * (1.f / (float)N_BATCH);
    }
}

// ---------------- launch ------------------------------------------------------
extern "C" void kernel_launch(void* const* d_in, const int* in_sizes, int n_in,
                              void* d_out, int out_size) {
    const float* x = (const float*)d_in[0];
    const float* y = (const float*)d_in[1];
    float* out = (float*)d_out;

    k_mean<<<C_DIM, 256>>>(y);
    k_norm<<<(N_BATCH * P_DIM) / 256, 256>>>(x, y);

    dim3 gg(P_DIM / BM, P_DIM / BN, N_BATCH);
    k_gemm_h<<<gg, 128>>>();

    k_rowcol<<<(N_BATCH * P_DIM) / R_CHUNK, 256>>>();

    dim3 gcb(P_DIM / 512, N_BATCH);
    k_colB<<<gcb, 256>>>();

    k_final<<<1, 32>>>(out);
}